// round 15
// baseline (speedup 1.0000x reference)
#include <cuda_runtime.h>
#include <cuda_fp16.h>
#include <cstdint>

#define D        64
#define K        1024
#define KEFF     192           // [xh | xh | xl] . [eh | el | eh]
#define M_TILE   128           // rows per CTA
#define NCHK     64            // codes per chunk
#define NCHUNK   (K / NCHK)    // 16
#define THREADS  128           // 4 warps, M=32 rows per warp
#define KS       200           // xs stride in halves (conflict-free A loads)

#define CHUNK_U4 1536          // uint4 per fragment-order chunk (24576 B)

// ---- dynamic smem layout (bytes) ----
#define XS_OFF   0                      // 128 x KS halves (51200)
#define HN_OFF   51200                  // float[1024]
#define BIDX_OFF 55296                  // int[128]
#define WSUM_OFF 55808                  // float[4]
#define FLAG_OFF 55824                  // int[1]
#define SM_TOTAL 55840

__device__ float g_hn[K];                            // 0.5*||e_k||^2
__device__ float g_ebt[K * D];                       // [K][D] fp32 (gather)
__device__ __align__(16) uint32_t g_bfrag[K * KEFF / 2]; // fragment-order B
__device__ float g_partials[1024];
__device__ unsigned g_ticket = 0;

__device__ __forceinline__ uint32_t pack2(__half lo, __half hi) {
    return (uint32_t)__half_as_ushort(lo) |
           ((uint32_t)__half_as_ushort(hi) << 16);
}

// ---------------------------------------------------------------------------
// prep: blocks [0,96)  -> fragment-order B  (24576 uint4)
//       blocks [96,160)-> transpose g_ebt + half-norms g_hn
// fragment mapping for mma.m16n8k16.row.col:
//   lane: q = lane&3, n4 = lane>>2; code = c*64 + nt*8 + n4
//   s-step s: kk = 16s + 2q; b0 = {v(kk), v(kk+1)}, b1 = {v(kk+8), v(kk+9)}
//   v(j): seg = j>>6 (0:eh, 1:el, 2:eh), d = j&63
// ---------------------------------------------------------------------------
__global__ void vq_prep(const float* __restrict__ emb) {
    const int b = blockIdx.x, t = threadIdx.x;
    if (b < 96) {
        int idx  = b * 256 + t;            // [0, 24576)
        int c    = idx / CHUNK_U4;
        int r    = idx - c * CHUNK_U4;
        int s2   = r >> 8;                 // 0..5
        int nt   = (r >> 5) & 7;
        int lane = r & 31;
        int q = lane & 3, n4 = lane >> 2;
        int code = c * 64 + nt * 8 + n4;
        uint32_t v[4];
#pragma unroll
        for (int h = 0; h < 2; ++h) {
            int s  = 2 * s2 + h;
            int kk = 16 * s + 2 * q;
            int seg = kk >> 6;
            int d0  = kk & 63;
            float e0 = emb[(size_t)(d0    ) * K + code];
            float e1 = emb[(size_t)(d0 + 1) * K + code];
            float e2 = emb[(size_t)(d0 + 8) * K + code];
            float e3 = emb[(size_t)(d0 + 9) * K + code];
            __half h0 = __float2half_rn(e0), h1 = __float2half_rn(e1);
            __half h2 = __float2half_rn(e2), h3 = __float2half_rn(e3);
            if (seg == 1) {
                h0 = __float2half_rn(e0 - __half2float(h0));
                h1 = __float2half_rn(e1 - __half2float(h1));
                h2 = __float2half_rn(e2 - __half2float(h2));
                h3 = __float2half_rn(e3 - __half2float(h3));
            }
            v[2 * h + 0] = pack2(h0, h1);
            v[2 * h + 1] = pack2(h2, h3);
        }
        ((uint4*)g_bfrag)[idx] = make_uint4(v[0], v[1], v[2], v[3]);
    } else {
        int i  = (b - 96) * 256 + t;       // [0, 16384)
        int k  = i >> 4;
        int d4 = (i & 15) << 2;
        float v0 = emb[(size_t)(d4 + 0) * K + k];
        float v1 = emb[(size_t)(d4 + 1) * K + k];
        float v2 = emb[(size_t)(d4 + 2) * K + k];
        float v3 = emb[(size_t)(d4 + 3) * K + k];
        *(float4*)&g_ebt[k * D + d4] = make_float4(v0, v1, v2, v3);
        float ps = v0 * v0 + v1 * v1 + v2 * v2 + v3 * v3;
#pragma unroll
        for (int o = 8; o; o >>= 1)
            ps += __shfl_down_sync(0xffffffffu, ps, o, 16);
        if ((t & 15) == 0) g_hn[k] = 0.5f * ps;
    }
}

// ---------------------------------------------------------------------------
__device__ __forceinline__ void mma16816(float& c0, float& c1, float& c2,
                                         float& c3, uint32_t a0, uint32_t a1,
                                         uint32_t a2, uint32_t a3,
                                         uint32_t b0, uint32_t b1) {
    asm volatile(
        "mma.sync.aligned.m16n8k16.row.col.f32.f16.f16.f32 "
        "{%0,%1,%2,%3}, {%4,%5,%6,%7}, {%8,%9}, {%0,%1,%2,%3};"
        : "+f"(c0), "+f"(c1), "+f"(c2), "+f"(c3)
        : "r"(a0), "r"(a1), "r"(a2), "r"(a3), "r"(b0), "r"(b1));
}

__global__ void __launch_bounds__(THREADS, 2)
vq_main(const float* __restrict__ x, float* __restrict__ out,
        float inv_total, int out_idx) {
    extern __shared__ char smem[];
    char*  xs   = smem + XS_OFF;
    float* hn   = (float*)(smem + HN_OFF);
    int*   bidx = (int*)  (smem + BIDX_OFF);
    float* wsum = (float*)(smem + WSUM_OFF);
    int*   flag = (int*)  (smem + FLAG_OFF);

    const int t    = threadIdx.x;
    const int w    = t >> 5;
    const int lane = t & 31;
    const int n4   = lane >> 2;
    const int q    = lane & 3;
    const int rowBase = blockIdx.x * M_TILE;

    // ---- half norms ----
#pragma unroll
    for (int i = 0; i < 8; ++i) hn[i * THREADS + t] = g_hn[i * THREADS + t];

    // ---- stage x tile: split fp32 -> [xh | xh | xl] fp16, stride KS ----
    const float4* xg = (const float4*)(x + (size_t)rowBase * D);
#pragma unroll
    for (int it = 0; it < 16; ++it) {
        int u = it * THREADS + t;
        int r = u >> 4, d = (u & 15) << 2;
        float4 v = xg[u];
        __half h0 = __float2half_rn(v.x), h1 = __float2half_rn(v.y);
        __half h2 = __float2half_rn(v.z), h3 = __float2half_rn(v.w);
        __half l0 = __float2half_rn(v.x - __half2float(h0));
        __half l1 = __float2half_rn(v.y - __half2float(h1));
        __half l2 = __float2half_rn(v.z - __half2float(h2));
        __half l3 = __float2half_rn(v.w - __half2float(h3));
        uint2 hv, lv;
        hv.x = pack2(h0, h1);
        hv.y = pack2(h2, h3);
        lv.x = pack2(l0, l1);
        lv.y = pack2(l2, l3);
        char* base = xs + r * (KS * 2) + d * 2;
        *(uint2*)(base)       = hv;
        *(uint2*)(base + 128) = hv;
        *(uint2*)(base + 256) = lv;
    }
    __syncthreads();

    // ---- preload A fragments: 12 ksteps x 2 mtiles (persistent) ----
    uint32_t afr[12][2][4];
#pragma unroll
    for (int mt = 0; mt < 2; ++mt) {
        const char* ab = xs + (w * 32 + mt * 16 + n4) * (KS * 2) + q * 4;
#pragma unroll
        for (int s = 0; s < 12; ++s) {
            afr[s][mt][0] = *(const uint32_t*)(ab + 32 * s);
            afr[s][mt][1] = *(const uint32_t*)(ab + 32 * s + 8 * (KS * 2));
            afr[s][mt][2] = *(const uint32_t*)(ab + 32 * s + 16);
            afr[s][mt][3] = *(const uint32_t*)(ab + 32 * s + 8 * (KS * 2) + 16);
        }
    }

    float bs[4];
    int   bi[4];
#pragma unroll
    for (int i = 0; i < 4; ++i) { bs[i] = -1e30f; bi[i] = 0; }

    // ---- mainloop: B fragments straight from gmem (L1/L2 resident),
    //      one-ahead register prefetch, NO barriers ----
    const uint4* gc = ((const uint4*)g_bfrag) + lane;
    for (int c = 0; c < NCHUNK; ++c) {
        const uint4* gb = gc + (size_t)c * CHUNK_U4;

        float acc[2][8][4];
#pragma unroll
        for (int mt = 0; mt < 2; ++mt)
#pragma unroll
            for (int nt = 0; nt < 8; ++nt)
#pragma unroll
                for (int i = 0; i < 4; ++i) acc[mt][nt][i] = 0.f;

        uint4 bv = __ldg(gb);
#pragma unroll
        for (int s2 = 0; s2 < 6; ++s2) {
#pragma unroll
            for (int nt = 0; nt < 8; ++nt) {
                const int i = s2 * 8 + nt;
                uint4 nb;
                if (i < 47) nb = __ldg(gb + (i + 1) * 32);
#pragma unroll
                for (int mt = 0; mt < 2; ++mt) {
                    mma16816(acc[mt][nt][0], acc[mt][nt][1],
                             acc[mt][nt][2], acc[mt][nt][3],
                             afr[2 * s2][mt][0], afr[2 * s2][mt][1],
                             afr[2 * s2][mt][2], afr[2 * s2][mt][3],
                             bv.x, bv.y);
                    mma16816(acc[mt][nt][0], acc[mt][nt][1],
                             acc[mt][nt][2], acc[mt][nt][3],
                             afr[2 * s2 + 1][mt][0], afr[2 * s2 + 1][mt][1],
                             afr[2 * s2 + 1][mt][2], afr[2 * s2 + 1][mt][3],
                             bv.z, bv.w);
                }
                bv = nb;
            }
        }

        // ---- epilogue: score = acc - hn, running argmax ----
#pragma unroll
        for (int mt = 0; mt < 2; ++mt) {
#pragma unroll
            for (int nt = 0; nt < 8; ++nt) {
                int cb = c * NCHK + nt * 8 + q * 2;
                float2 h = *(const float2*)&hn[cb];
                float s0 = acc[mt][nt][0] - h.x;
                float s1 = acc[mt][nt][1] - h.y;
                float s2v = acc[mt][nt][2] - h.x;
                float s3 = acc[mt][nt][3] - h.y;
                if (s0 > bs[mt * 2])      { bs[mt * 2] = s0;      bi[mt * 2] = cb; }
                if (s1 > bs[mt * 2])      { bs[mt * 2] = s1;      bi[mt * 2] = cb + 1; }
                if (s2v > bs[mt * 2 + 1]) { bs[mt * 2 + 1] = s2v; bi[mt * 2 + 1] = cb; }
                if (s3 > bs[mt * 2 + 1])  { bs[mt * 2 + 1] = s3;  bi[mt * 2 + 1] = cb + 1; }
            }
        }
    }

    // ---- reduce (score, idx) across the 4 lanes sharing each row ----
#pragma unroll
    for (int off = 1; off <= 2; off <<= 1) {
#pragma unroll
        for (int i = 0; i < 4; ++i) {
            float os = __shfl_xor_sync(0xffffffffu, bs[i], off);
            int   oi = __shfl_xor_sync(0xffffffffu, bi[i], off);
            if (os > bs[i] || (os == bs[i] && oi < bi[i])) {
                bs[i] = os; bi[i] = oi;
            }
        }
    }
    if (q == 0) {
#pragma unroll
        for (int mt = 0; mt < 2; ++mt) {
            bidx[w * 32 + mt * 16 + n4]     = bi[mt * 2];
            bidx[w * 32 + mt * 16 + n4 + 8] = bi[mt * 2 + 1];
        }
    }
    __syncthreads();

    // ---- gather quantized rows + partial MSE ----
    float lsum = 0.f;
    const float4* ebt4 = (const float4*)g_ebt;
    float4* of4 = (float4*)(out + (size_t)rowBase * D);
#pragma unroll
    for (int it = 0; it < 16; ++it) {
        int u = it * THREADS + t;          // float4 idx in [0, 2048)
        int r = u >> 4, d4 = u & 15;
        int b = bidx[r];
        float4 qv = ebt4[b * 16 + d4];
        float4 xv = xg[u];
        of4[u] = qv;
        float dx = qv.x - xv.x, dy = qv.y - xv.y;
        float dz = qv.z - xv.z, dw = qv.w - xv.w;
        lsum = fmaf(dx, dx, lsum);
        lsum = fmaf(dy, dy, lsum);
        lsum = fmaf(dz, dz, lsum);
        lsum = fmaf(dw, dw, lsum);
    }
#pragma unroll
    for (int o = 16; o; o >>= 1) lsum += __shfl_down_sync(0xffffffffu, lsum, o);
    if (lane == 0) wsum[w] = lsum;
    __syncthreads();

    // ---- last-CTA loss finalization (deterministic fixed-order sum) ----
    if (t == 0) {
        float s = wsum[0] + wsum[1] + wsum[2] + wsum[3];
        g_partials[blockIdx.x] = s;
        __threadfence();
        unsigned tk = atomicAdd(&g_ticket, 1u);
        flag[0] = (tk == gridDim.x - 1) ? 1 : 0;
    }
    __syncthreads();
    if (flag[0]) {
        const int ncta = gridDim.x;
        volatile const float* gp = g_partials;
        float s = 0.f;
        for (int i = t; i < ncta; i += THREADS) s += gp[i];
#pragma unroll
        for (int o = 16; o; o >>= 1)
            s += __shfl_down_sync(0xffffffffu, s, o);
        if (lane == 0) wsum[w] = s;
        __syncthreads();
        if (t == 0) {
            float tot = wsum[0] + wsum[1] + wsum[2] + wsum[3];
            out[out_idx] = 1.25f * tot * inv_total;
            g_ticket = 0;                  // reset for graph replay
        }
    }
}

// ---------------------------------------------------------------------------
extern "C" void kernel_launch(void* const* d_in, const int* in_sizes, int n_in,
                              void* d_out, int out_size) {
    const float* x   = (const float*)d_in[0];   // [N, 64]
    const float* emb = (const float*)d_in[1];   // [64, 1024]
    float* out = (float*)d_out;

    int nelem = in_sizes[0];
    int nrows = nelem / D;
    int ncta  = nrows / M_TILE;                 // 512

    cudaFuncSetAttribute(vq_main, cudaFuncAttributeMaxDynamicSharedMemorySize,
                         SM_TOTAL);

    vq_prep<<<160, 256>>>(emb);
    vq_main<<<ncta, THREADS, SM_TOTAL>>>(x, out, 1.0f / (float)nelem,
                                         out_size - 1);
}

// round 17
// speedup vs baseline: 1.4115x; 1.4115x over previous
#include <cuda_runtime.h>
#include <cuda_fp16.h>
#include <cstdint>

#define D        64
#define K        1024
#define KEFF     192           // [xh | xh | xl] . [eh | el | eh]
#define M_TILE   128           // rows per CTA
#define NCHK     32            // codes per chunk
#define NCHUNK   (K / NCHK)    // 32
#define THREADS  128           // 4 warps, M=32 rows per warp
#define KS2      136           // xs stride in halves (272 B, dedup layout)

#define CHUNK_U4 768           // uint4 per fragment-order chunk (12288 B)

// ---- dynamic smem layout (bytes) ----
#define ES0_OFF  0                      // chunk buffer 0 (12288)
#define ES1_OFF  12288                  // chunk buffer 1 (12288)
#define XS_OFF   24576                  // 128 x KS2 halves (34816)
#define HN_OFF   59392                  // float[1024]
#define BIDX_OFF 63488                  // int[128]
#define WSUM_OFF 64000                  // float[4]
#define FLAG_OFF 64016                  // int[1]
#define SM_TOTAL 64032

__device__ float g_hn[K];                            // 0.5*||e_k||^2
__device__ float g_ebt[K * D];                       // [K][D] fp32 (gather)
__device__ __align__(16) uint32_t g_bfrag[K * KEFF / 2]; // fragment-order B
__device__ float g_partials[1024];
__device__ unsigned g_ticket = 0;

__device__ __forceinline__ uint32_t pack2(__half lo, __half hi) {
    return (uint32_t)__half_as_ushort(lo) |
           ((uint32_t)__half_as_ushort(hi) << 16);
}
__device__ __forceinline__ uint32_t smem_u32(const void* p) {
    uint32_t a;
    asm("{ .reg .u64 t; cvta.to.shared.u64 t, %1; cvt.u32.u64 %0, t; }"
        : "=r"(a) : "l"(p));
    return a;
}
__device__ __forceinline__ void cp16(uint32_t dst, const void* src) {
    asm volatile("cp.async.cg.shared.global [%0], [%1], 16;"
                 :: "r"(dst), "l"(src));
}
#define CP_COMMIT() asm volatile("cp.async.commit_group;" ::: "memory")
#define CP_WAIT0()  asm volatile("cp.async.wait_group 0;" ::: "memory")

// ---------------------------------------------------------------------------
// prep: blocks [0,96)  -> fragment-order B  (24576 uint4, NCHK=32 chunks)
//       blocks [96,160)-> transpose g_ebt + half-norms g_hn
// fragment mapping for mma.m16n8k16.row.col:
//   lane: q = lane&3, n4 = lane>>2; code = c*32 + nt*8 + n4   (nt in 0..3)
//   s-step s: kk = 16s + 2q; b0 = {v(kk), v(kk+1)}, b1 = {v(kk+8), v(kk+9)}
//   v(j): seg = j>>6 (0:eh, 1:el, 2:eh), d = j&63
// ---------------------------------------------------------------------------
__global__ void vq_prep(const float* __restrict__ emb) {
    const int b = blockIdx.x, t = threadIdx.x;
    if (b < 96) {
        int idx  = b * 256 + t;            // [0, 24576)
        int c    = idx / CHUNK_U4;
        int r    = idx - c * CHUNK_U4;
        int s2   = r >> 7;                 // 0..5
        int nt   = (r >> 5) & 3;
        int lane = r & 31;
        int q = lane & 3, n4 = lane >> 2;
        int code = c * NCHK + nt * 8 + n4;
        uint32_t v[4];
#pragma unroll
        for (int h = 0; h < 2; ++h) {
            int s  = 2 * s2 + h;
            int kk = 16 * s + 2 * q;
            int seg = kk >> 6;
            int d0  = kk & 63;
            float e0 = emb[(size_t)(d0    ) * K + code];
            float e1 = emb[(size_t)(d0 + 1) * K + code];
            float e2 = emb[(size_t)(d0 + 8) * K + code];
            float e3 = emb[(size_t)(d0 + 9) * K + code];
            __half h0 = __float2half_rn(e0), h1 = __float2half_rn(e1);
            __half h2 = __float2half_rn(e2), h3 = __float2half_rn(e3);
            if (seg == 1) {
                h0 = __float2half_rn(e0 - __half2float(h0));
                h1 = __float2half_rn(e1 - __half2float(h1));
                h2 = __float2half_rn(e2 - __half2float(h2));
                h3 = __float2half_rn(e3 - __half2float(h3));
            }
            v[2 * h + 0] = pack2(h0, h1);
            v[2 * h + 1] = pack2(h2, h3);
        }
        ((uint4*)g_bfrag)[idx] = make_uint4(v[0], v[1], v[2], v[3]);
    } else {
        int i  = (b - 96) * 256 + t;       // [0, 16384)
        int k  = i >> 4;
        int d4 = (i & 15) << 2;
        float v0 = emb[(size_t)(d4 + 0) * K + k];
        float v1 = emb[(size_t)(d4 + 1) * K + k];
        float v2 = emb[(size_t)(d4 + 2) * K + k];
        float v3 = emb[(size_t)(d4 + 3) * K + k];
        *(float4*)&g_ebt[k * D + d4] = make_float4(v0, v1, v2, v3);
        float ps = v0 * v0 + v1 * v1 + v2 * v2 + v3 * v3;
#pragma unroll
        for (int o = 8; o; o >>= 1)
            ps += __shfl_down_sync(0xffffffffu, ps, o, 16);
        if ((t & 15) == 0) g_hn[k] = 0.5f * ps;
    }
}

// ---------------------------------------------------------------------------
__device__ __forceinline__ void mma16816(float& c0, float& c1, float& c2,
                                         float& c3, uint32_t a0, uint32_t a1,
                                         uint32_t a2, uint32_t a3,
                                         uint32_t b0, uint32_t b1) {
    asm volatile(
        "mma.sync.aligned.m16n8k16.row.col.f32.f16.f16.f32 "
        "{%0,%1,%2,%3}, {%4,%5,%6,%7}, {%8,%9}, {%0,%1,%2,%3};"
        : "+f"(c0), "+f"(c1), "+f"(c2), "+f"(c3)
        : "r"(a0), "r"(a1), "r"(a2), "r"(a3), "r"(b0), "r"(b1));
}

__global__ void __launch_bounds__(THREADS, 3)
vq_main(const float* __restrict__ x, float* __restrict__ out,
        float inv_total, int out_idx) {
    extern __shared__ char smem[];
    char*  xs   = smem + XS_OFF;
    float* hn   = (float*)(smem + HN_OFF);
    int*   bidx = (int*)  (smem + BIDX_OFF);
    float* wsum = (float*)(smem + WSUM_OFF);
    int*   flag = (int*)  (smem + FLAG_OFF);
    const uint32_t sb = smem_u32(smem);

    const int t    = threadIdx.x;
    const int w    = t >> 5;
    const int lane = t & 31;
    const int n4   = lane >> 2;
    const int q    = lane & 3;
    const int rowBase = blockIdx.x * M_TILE;

    // ---- prefetch chunk 0 via cp.async (overlaps A staging) ----
    const uint4* gB = (const uint4*)g_bfrag;
#pragma unroll
    for (int j = 0; j < 6; ++j)
        cp16(sb + ES0_OFF + (j * THREADS + t) * 16, gB + j * THREADS + t);
    CP_COMMIT();

    // ---- half norms ----
#pragma unroll
    for (int i = 0; i < 8; ++i) hn[i * THREADS + t] = g_hn[i * THREADS + t];

    // ---- stage x tile: split fp32 -> [xh | xl] fp16 (dedup), stride KS2 ----
    const float4* xg = (const float4*)(x + (size_t)rowBase * D);
#pragma unroll
    for (int it = 0; it < 16; ++it) {
        int u = it * THREADS + t;
        int r = u >> 4, d = (u & 15) << 2;
        float4 v = xg[u];
        __half h0 = __float2half_rn(v.x), h1 = __float2half_rn(v.y);
        __half h2 = __float2half_rn(v.z), h3 = __float2half_rn(v.w);
        __half l0 = __float2half_rn(v.x - __half2float(h0));
        __half l1 = __float2half_rn(v.y - __half2float(h1));
        __half l2 = __float2half_rn(v.z - __half2float(h2));
        __half l3 = __float2half_rn(v.w - __half2float(h3));
        uint2 hv, lv;
        hv.x = pack2(h0, h1);
        hv.y = pack2(h2, h3);
        lv.x = pack2(l0, l1);
        lv.y = pack2(l2, l3);
        char* base = xs + r * (KS2 * 2) + d * 2;
        *(uint2*)(base)       = hv;          // xh at bytes [0,128)
        *(uint2*)(base + 128) = lv;          // xl at bytes [128,256)
    }
    __syncthreads();

    // ---- preload A fragments (dedup): 4 xh + 4 xl ksteps x 2 mtiles ----
    uint32_t afr_h[4][2][4], afr_l[4][2][4];
#pragma unroll
    for (int mt = 0; mt < 2; ++mt) {
        const char* ab = xs + (w * 32 + mt * 16 + n4) * (KS2 * 2) + q * 4;
#pragma unroll
        for (int s = 0; s < 4; ++s) {
            afr_h[s][mt][0] = *(const uint32_t*)(ab + 32 * s);
            afr_h[s][mt][1] = *(const uint32_t*)(ab + 32 * s + 8 * (KS2 * 2));
            afr_h[s][mt][2] = *(const uint32_t*)(ab + 32 * s + 16);
            afr_h[s][mt][3] = *(const uint32_t*)(ab + 32 * s + 8 * (KS2 * 2) + 16);
            afr_l[s][mt][0] = *(const uint32_t*)(ab + 128 + 32 * s);
            afr_l[s][mt][1] = *(const uint32_t*)(ab + 128 + 32 * s + 8 * (KS2 * 2));
            afr_l[s][mt][2] = *(const uint32_t*)(ab + 128 + 32 * s + 16);
            afr_l[s][mt][3] = *(const uint32_t*)(ab + 128 + 32 * s + 8 * (KS2 * 2) + 16);
        }
    }

    float bs[4];
    int   bi[4];
#pragma unroll
    for (int i = 0; i < 4; ++i) { bs[i] = -1e30f; bi[i] = 0; }

    for (int c = 0; c < NCHUNK; ++c) {
        CP_WAIT0();
        __syncthreads();                  // chunk c visible; other buf free

        if (c + 1 < NCHUNK) {             // prefetch c+1 into other buffer
            uint32_t dst = sb + (((c + 1) & 1) ? ES1_OFF : ES0_OFF);
            const uint4* gc = gB + (size_t)(c + 1) * CHUNK_U4;
#pragma unroll
            for (int j = 0; j < 6; ++j)
                cp16(dst + (j * THREADS + t) * 16, gc + j * THREADS + t);
            CP_COMMIT();
        }

        const char* esb = smem + ((c & 1) ? ES1_OFF : ES0_OFF);
        float acc[2][4][4];
#pragma unroll
        for (int mt = 0; mt < 2; ++mt)
#pragma unroll
            for (int nt = 0; nt < 4; ++nt)
#pragma unroll
                for (int i = 0; i < 4; ++i) acc[mt][nt][i] = 0.f;

        // kstep s: frag = s<8 ? afr_h[s&3] : afr_l[s&3]  ([xh|xh|xl] dedup)
#pragma unroll
        for (int s2 = 0; s2 < 6; ++s2) {
            const int sA = 2 * s2, sB = 2 * s2 + 1;
            const uint32_t (*fA)[4] = (sA < 8) ? afr_h[sA & 3] : afr_l[sA & 3];
            const uint32_t (*fB)[4] = (sB < 8) ? afr_h[sB & 3] : afr_l[sB & 3];
#pragma unroll
            for (int nt = 0; nt < 4; ++nt) {
                uint4 bv = *(const uint4*)(esb +
                    (((s2 * 4 + nt) * 32) + lane) * 16);
#pragma unroll
                for (int mt = 0; mt < 2; ++mt) {
                    mma16816(acc[mt][nt][0], acc[mt][nt][1],
                             acc[mt][nt][2], acc[mt][nt][3],
                             fA[mt][0], fA[mt][1], fA[mt][2], fA[mt][3],
                             bv.x, bv.y);
                    mma16816(acc[mt][nt][0], acc[mt][nt][1],
                             acc[mt][nt][2], acc[mt][nt][3],
                             fB[mt][0], fB[mt][1], fB[mt][2], fB[mt][3],
                             bv.z, bv.w);
                }
            }
        }

        // ---- epilogue: score = acc - hn, running argmax ----
#pragma unroll
        for (int mt = 0; mt < 2; ++mt) {
#pragma unroll
            for (int nt = 0; nt < 4; ++nt) {
                int cb = c * NCHK + nt * 8 + q * 2;
                float2 h = *(const float2*)&hn[cb];
                float s0 = acc[mt][nt][0] - h.x;
                float s1 = acc[mt][nt][1] - h.y;
                float s2v = acc[mt][nt][2] - h.x;
                float s3 = acc[mt][nt][3] - h.y;
                if (s0 > bs[mt * 2])      { bs[mt * 2] = s0;      bi[mt * 2] = cb; }
                if (s1 > bs[mt * 2])      { bs[mt * 2] = s1;      bi[mt * 2] = cb + 1; }
                if (s2v > bs[mt * 2 + 1]) { bs[mt * 2 + 1] = s2v; bi[mt * 2 + 1] = cb; }
                if (s3 > bs[mt * 2 + 1])  { bs[mt * 2 + 1] = s3;  bi[mt * 2 + 1] = cb + 1; }
            }
        }
    }

    // ---- reduce (score, idx) across the 4 lanes sharing each row ----
#pragma unroll
    for (int off = 1; off <= 2; off <<= 1) {
#pragma unroll
        for (int i = 0; i < 4; ++i) {
            float os = __shfl_xor_sync(0xffffffffu, bs[i], off);
            int   oi = __shfl_xor_sync(0xffffffffu, bi[i], off);
            if (os > bs[i] || (os == bs[i] && oi < bi[i])) {
                bs[i] = os; bi[i] = oi;
            }
        }
    }
    if (q == 0) {
#pragma unroll
        for (int mt = 0; mt < 2; ++mt) {
            bidx[w * 32 + mt * 16 + n4]     = bi[mt * 2];
            bidx[w * 32 + mt * 16 + n4 + 8] = bi[mt * 2 + 1];
        }
    }
    __syncthreads();

    // ---- gather quantized rows + partial MSE ----
    float lsum = 0.f;
    const float4* ebt4 = (const float4*)g_ebt;
    float4* of4 = (float4*)(out + (size_t)rowBase * D);
#pragma unroll
    for (int it = 0; it < 16; ++it) {
        int u = it * THREADS + t;          // float4 idx in [0, 2048)
        int r = u >> 4, d4 = u & 15;
        int b = bidx[r];
        float4 qv = ebt4[b * 16 + d4];
        float4 xv = xg[u];
        of4[u] = qv;
        float dx = qv.x - xv.x, dy = qv.y - xv.y;
        float dz = qv.z - xv.z, dw = qv.w - xv.w;
        lsum = fmaf(dx, dx, lsum);
        lsum = fmaf(dy, dy, lsum);
        lsum = fmaf(dz, dz, lsum);
        lsum = fmaf(dw, dw, lsum);
    }
#pragma unroll
    for (int o = 16; o; o >>= 1) lsum += __shfl_down_sync(0xffffffffu, lsum, o);
    if (lane == 0) wsum[w] = lsum;
    __syncthreads();

    // ---- last-CTA loss finalization (deterministic fixed-order sum) ----
    if (t == 0) {
        float s = wsum[0] + wsum[1] + wsum[2] + wsum[3];
        g_partials[blockIdx.x] = s;
        __threadfence();
        unsigned tk = atomicAdd(&g_ticket, 1u);
        flag[0] = (tk == gridDim.x - 1) ? 1 : 0;
    }
    __syncthreads();
    if (flag[0]) {
        const int ncta = gridDim.x;
        volatile const float* gp = g_partials;
        float s = 0.f;
        for (int i = t; i < ncta; i += THREADS) s += gp[i];
#pragma unroll
        for (int o = 16; o; o >>= 1)
            s += __shfl_down_sync(0xffffffffu, s, o);
        if (lane == 0) wsum[w] = s;
        __syncthreads();
        if (t == 0) {
            float tot = wsum[0] + wsum[1] + wsum[2] + wsum[3];
            out[out_idx] = 1.25f * tot * inv_total;
            g_ticket = 0;                  // reset for graph replay
        }
    }
}

// ---------------------------------------------------------------------------
extern "C" void kernel_launch(void* const* d_in, const int* in_sizes, int n_in,
                              void* d_out, int out_size) {
    const float* x   = (const float*)d_in[0];   // [N, 64]
    const float* emb = (const float*)d_in[1];   // [64, 1024]
    float* out = (float*)d_out;

    int nelem = in_sizes[0];
    int nrows = nelem / D;
    int ncta  = nrows / M_TILE;                 // 512

    cudaFuncSetAttribute(vq_main, cudaFuncAttributeMaxDynamicSharedMemorySize,
                         SM_TOTAL);

    vq_prep<<<160, 256>>>(emb);
    vq_main<<<ncta, THREADS, SM_TOTAL>>>(x, out, 1.0f / (float)nelem,
                                         out_size - 1);
}